// round 12
// baseline (speedup 1.0000x reference)
#include <cuda_runtime.h>
#include <cuda_fp16.h>
#include <math.h>

#define NB 32
#define NN 1024
#define L2E 1.4426950408889634f
#define RPC 16                   // rows per CTA
#define ITERS 20

// Static scratch (no allocation allowed). d_P = 64 MB fp16, L2-resident.
__device__ __half d_P[(size_t)NB * NN * NN];
__device__ float  d_r[NB * NN];               // last-iteration row scalings
// Rotating column accumulators: iter k reads buf[k] (c=1/buf[k]), TMA-reduces
// into buf[k+1]. buf[1..ITERS] zeroed once per launch.
__device__ float  d_colacc[ITERS + 1][NB * NN];

// ---------------------------------------------------------------------------
__device__ __forceinline__ unsigned smem_u32(const void* p) {
    return (unsigned)__cvta_generic_to_shared(p);
}

// One 4 KB smem->global add-reduction via the TMA engine (replaces 1024
// per-thread atomics). Caller guarantees smem partials are complete.
__device__ __forceinline__ void bulk_reduce_add_4k(float* gdst, const float* ssrc) {
    asm volatile("fence.proxy.async.shared::cta;" ::: "memory");
    asm volatile(
        "cp.reduce.async.bulk.global.shared::cta.bulk_group.add.f32 [%0], [%1], %2;"
        :: "l"(gdst), "r"(smem_u32(ssrc)), "r"(NN * 4) : "memory");
    asm volatile("cp.async.bulk.commit_group;" ::: "memory");
    asm volatile("cp.async.bulk.wait_group 0;" ::: "memory");
}

// ---------------------------------------------------------------------------
// Zero buf[1..ITERS].
__global__ __launch_bounds__(512) void init_kernel() {
    ((float*)&d_colacc[1][0])[blockIdx.x * 512 + threadIdx.x] = 0.0f;
}

// ---------------------------------------------------------------------------
// Fused precompute + iteration 0. 64 CTAs/batch, 16 rows each (warp/row).
//   P_ij = exp2(g*L2E - M_i)  -> gmem (fp16) and smem tile
//   r^1_i = 1/sum_j P_ij      -> d_r (overwritten later; harmless)
//   colacc[1]_j += sum_i P_ij r^1_i   (TMA bulk reduce)
__global__ __launch_bounds__(512)
void pre_iter0_kernel(const float* __restrict__ g) {
    extern __shared__ float smem[];
    __half* s_P = (__half*)smem;                 // RPC*NN halfs = 32 KB
    float*  s_c = smem + RPC * NN / 2;           // NN floats (col partials)
    float*  s_r = s_c + NN;                      // RPC floats

    const int tid  = threadIdx.x;
    const int b    = blockIdx.x >> 6;
    const int cib  = blockIdx.x & 63;
    const int warp = tid >> 5, lane = tid & 31;
    const int row  = (b << 10) + cib * RPC + warp;

    const float4* gr = (const float4*)(g + (size_t)row * NN);
    float4 v[8];
    float m = -1e30f;
#pragma unroll
    for (int k = 0; k < 8; k++) {
        v[k] = gr[lane + 32 * k];
        m = fmaxf(m, fmaxf(fmaxf(v[k].x, v[k].y), fmaxf(v[k].z, v[k].w)));
    }
#pragma unroll
    for (int o = 16; o; o >>= 1)
        m = fmaxf(m, __shfl_xor_sync(0xffffffffu, m, o));
    const float mb = m * L2E;

    uint2* pg = (uint2*)(d_P + (size_t)row * NN);
    uint2* sp = (uint2*)(s_P + warp * NN);
    float  s  = 0.0f;
#pragma unroll
    for (int k = 0; k < 8; k++) {
        const int idx = lane + 32 * k;
        const float ex = exp2f(fmaf(v[k].x, L2E, -mb));
        const float ey = exp2f(fmaf(v[k].y, L2E, -mb));
        const float ez = exp2f(fmaf(v[k].z, L2E, -mb));
        const float ew = exp2f(fmaf(v[k].w, L2E, -mb));
        __half2 h0 = __floats2half2_rn(ex, ey);
        __half2 h1 = __floats2half2_rn(ez, ew);
        uint2 u;
        u.x = *(const unsigned*)&h0;
        u.y = *(const unsigned*)&h1;
        pg[idx] = u;
        sp[idx] = u;
        s += (ex + ey) + (ez + ew);
    }
#pragma unroll
    for (int o = 16; o; o >>= 1)
        s += __shfl_xor_sync(0xffffffffu, s, o);
    const float r = __fdividef(1.0f, s);
    if (lane == 0) s_r[warp] = r;
    __syncthreads();

    float iv[RPC];
#pragma unroll
    for (int i = 0; i < RPC; i++) iv[i] = s_r[i];

    const __half2* sp2 = (const __half2*)s_P;
    float cx = 0.0f, cy = 0.0f;
#pragma unroll
    for (int i = 0; i < RPC; i++) {
        const float2 f = __half22float2(sp2[i * 512 + tid]);
        cx = fmaf(f.x, iv[i], cx);
        cy = fmaf(f.y, iv[i], cy);
    }
    ((float2*)s_c)[tid] = make_float2(cx, cy);
    __syncthreads();

    if (tid == 0) bulk_reduce_add_4k(&d_colacc[1][b << 10], s_c);
}

// ---------------------------------------------------------------------------
// Sinkhorn iteration k (k = 1..19). 64 CTAs/batch, 16 rows each.
// No smem P staging: phase A reads the tile with L1-caching LDG.128; phase B
// re-reads the (L1-hot) tile column-wise — one 128B line per warp per row.
//   c_j = 1/colacc[k][j] -> smem
//   r_i = 1/sum_j P_ij c_j            (warp/row)
//   colacc[k+1]_j += sum_i P_ij r_i   (TMA bulk reduce)
__global__ __launch_bounds__(512, 3)
void iter_kernel(int k) {
    __shared__ float s_c[NN];    // c, then reused for column partials
    __shared__ float s_r[RPC];

    const int tid  = threadIdx.x;
    const int b    = blockIdx.x >> 6;
    const int cib  = blockIdx.x & 63;
    const int warp = tid >> 5, lane = tid & 31;

    {
        const float* br = &d_colacc[k][b << 10];
        s_c[tid]       = __fdividef(1.0f, br[tid]);
        s_c[tid + 512] = __fdividef(1.0f, br[tid + 512]);
    }
    __syncthreads();

    const int rowbase = (b << 10) + cib * RPC;
    const int row     = rowbase + warp;
    const uint4*  pr  = (const uint4*)(d_P + (size_t)row * NN);
    const float4* c4  = (const float4*)s_c;

    // ---- phase A: warp per row, 4 x LDG.128 (32 halves/thread) ----
    float s = 0.0f;
#pragma unroll
    for (int kk = 0; kk < 4; kk++) {
        const int idx = lane + 32 * kk;          // uint4 slot 0..127
        const uint4 pv = pr[idx];
        const float4 ca = c4[2 * idx];
        const float4 cb = c4[2 * idx + 1];
        const __half2* h = (const __half2*)&pv;
        const float2 f0 = __half22float2(h[0]);
        const float2 f1 = __half22float2(h[1]);
        const float2 f2 = __half22float2(h[2]);
        const float2 f3 = __half22float2(h[3]);
        s = fmaf(f0.x, ca.x, s);
        s = fmaf(f0.y, ca.y, s);
        s = fmaf(f1.x, ca.z, s);
        s = fmaf(f1.y, ca.w, s);
        s = fmaf(f2.x, cb.x, s);
        s = fmaf(f2.y, cb.y, s);
        s = fmaf(f3.x, cb.z, s);
        s = fmaf(f3.y, cb.w, s);
    }
#pragma unroll
    for (int o = 16; o; o >>= 1)
        s += __shfl_xor_sync(0xffffffffu, s, o);
    const float r = __fdividef(1.0f, s);
    if (lane == 0) {
        s_r[warp] = r;
        if (k == ITERS - 1) d_r[row] = r;        // only last r feeds final
    }
    __syncthreads();   // s_r ready; all phase-A reads of s_c complete

    // ---- phase B: thread owns 2 adjacent columns; P rows hit L1 ----
    float iv[RPC];
#pragma unroll
    for (int i = 0; i < RPC; i++) iv[i] = s_r[i];

    const __half2* pcol = (const __half2*)(d_P + (size_t)rowbase * NN) + tid;
    float cx = 0.0f, cy = 0.0f;
#pragma unroll
    for (int i = 0; i < RPC; i++) {
        const float2 f = __half22float2(pcol[i * (NN / 2)]);
        cx = fmaf(f.x, iv[i], cx);
        cy = fmaf(f.y, iv[i], cy);
    }
    ((float2*)s_c)[tid] = make_float2(cx, cy);
    __syncthreads();

    if (tid == 0) bulk_reduce_add_4k(&d_colacc[k + 1][b << 10], s_c);
}

// ---------------------------------------------------------------------------
// Final: out_ij = P_ij * r_i * c_j with c_j = 1/colacc[ITERS][j].
// P read from (hot) L2 in fp16 — no exp2, no g re-read. Warp per row.
__global__ __launch_bounds__(256) void final_kernel(float* __restrict__ out) {
    __shared__ float s_ci[NN];
    const int row0 = blockIdx.x * 8;
    const int b    = row0 >> 10;

    for (int t = threadIdx.x; t < NN; t += 256)
        s_ci[t] = __fdividef(1.0f, d_colacc[ITERS][(b << 10) + t]);
    __syncthreads();

    const int warp = threadIdx.x >> 5, lane = threadIdx.x & 31;
    const int row  = row0 + warp;
    const float rv = d_r[row];

    const uint2*  pr  = (const uint2*)(d_P + (size_t)row * NN);
    const float4* ci4 = (const float4*)s_ci;
    float4*       orw = (float4*)(out + (size_t)row * NN);

#pragma unroll
    for (int k = 0; k < 8; k++) {
        const int idx = lane + 32 * k;
        const uint2 pv = __ldcg(&pr[idx]);
        const float2 f0 = __half22float2(*(const __half2*)&pv.x);
        const float2 f1 = __half22float2(*(const __half2*)&pv.y);
        const float4 cv = ci4[idx];
        float4 o;
        o.x = f0.x * rv * cv.x;
        o.y = f0.y * rv * cv.y;
        o.z = f1.x * rv * cv.z;
        o.w = f1.y * rv * cv.w;
        orw[idx] = o;
    }
}

// ---------------------------------------------------------------------------
extern "C" void kernel_launch(void* const* d_in, const int* in_sizes, int n_in,
                              void* d_out, int out_size) {
    // Only the gumbel tensor matters (score projection cancels in the first
    // row normalization).
    const float* g = nullptr;
    for (int i = 0; i < n_in; i++)
        if (in_sizes[i] == NB * NN * NN) g = (const float*)d_in[i];
    float* out = (float*)d_out;

    const int PRE_SMEM = RPC * NN * 2 + NN * 4 + RPC * 4;   // 36928
    cudaFuncSetAttribute(pre_iter0_kernel,
                         cudaFuncAttributeMaxDynamicSharedMemorySize, PRE_SMEM);

    init_kernel<<<ITERS * NB * NN / 512, 512>>>();            // zero buf[1..20]
    pre_iter0_kernel<<<NB * (NN / RPC), 512, PRE_SMEM>>>(g);  // P + iter 0

    for (int it = 1; it < ITERS; it++)
        iter_kernel<<<NB * (NN / RPC), 512>>>(it);

    final_kernel<<<NB * NN / 8, 256>>>(out);
}

// round 13
// speedup vs baseline: 1.1414x; 1.1414x over previous
#include <cuda_runtime.h>
#include <cuda_fp16.h>
#include <math.h>

#define NB 32
#define NN 1024
#define L2E 1.4426950408889634f
#define RPC 16                   // rows per CTA
#define ITERS 20

// Static scratch (no allocation allowed). d_P = 64 MB fp16, L2-resident.
__device__ __half d_P[(size_t)NB * NN * NN];
__device__ float  d_r[NB * NN];               // last-iteration row scalings
// Rotating column accumulators: iter k reads buf[k] (c=1/buf[k]), TMA-reduces
// into buf[k+1]. buf[1..ITERS] zeroed once per launch.
__device__ float  d_colacc[ITERS + 1][NB * NN];

// ---------------------------------------------------------------------------
__device__ __forceinline__ unsigned smem_u32(const void* p) {
    return (unsigned)__cvta_generic_to_shared(p);
}

// One 4 KB smem->global add-reduction via the TMA engine (replaces 1024
// per-thread atomics). Caller guarantees smem partials are complete.
__device__ __forceinline__ void bulk_reduce_add_4k(float* gdst, const float* ssrc) {
    asm volatile("fence.proxy.async.shared::cta;" ::: "memory");
    asm volatile(
        "cp.reduce.async.bulk.global.shared::cta.bulk_group.add.f32 [%0], [%1], %2;"
        :: "l"(gdst), "r"(smem_u32(ssrc)), "r"(NN * 4) : "memory");
    asm volatile("cp.async.bulk.commit_group;" ::: "memory");
    asm volatile("cp.async.bulk.wait_group 0;" ::: "memory");
}

// ---------------------------------------------------------------------------
// Zero buf[1..ITERS].
__global__ __launch_bounds__(512) void init_kernel() {
    ((float*)&d_colacc[1][0])[blockIdx.x * 512 + threadIdx.x] = 0.0f;
}

// ---------------------------------------------------------------------------
// Fused precompute + iteration 0. 64 CTAs/batch, 16 rows each (warp/row).
//   P_ij = exp2(g*L2E - M_i)  -> gmem (fp16) and smem tile
//   r^1_i = 1/sum_j P_ij
//   colacc[1]_j += sum_i P_ij r^1_i   (fp16 HFMA2 partials, TMA bulk reduce)
__global__ __launch_bounds__(512)
void pre_iter0_kernel(const float* __restrict__ g) {
    extern __shared__ float smem[];
    __half*  s_P  = (__half*)smem;                 // RPC*NN halfs = 32 KB
    float*   s_c  = smem + RPC * NN / 2;           // NN floats (col partials)
    __half2* s_rh = (__half2*)(s_c + NN);          // RPC half2 (r broadcast)

    const int tid  = threadIdx.x;
    const int b    = blockIdx.x >> 6;
    const int cib  = blockIdx.x & 63;
    const int warp = tid >> 5, lane = tid & 31;
    const int row  = (b << 10) + cib * RPC + warp;

    const float4* gr = (const float4*)(g + (size_t)row * NN);
    float4 v[8];
    float m = -1e30f;
#pragma unroll
    for (int k = 0; k < 8; k++) {
        v[k] = gr[lane + 32 * k];
        m = fmaxf(m, fmaxf(fmaxf(v[k].x, v[k].y), fmaxf(v[k].z, v[k].w)));
    }
#pragma unroll
    for (int o = 16; o; o >>= 1)
        m = fmaxf(m, __shfl_xor_sync(0xffffffffu, m, o));
    const float mb = m * L2E;

    uint2* pg = (uint2*)(d_P + (size_t)row * NN);
    uint2* sp = (uint2*)(s_P + warp * NN);
    float  s  = 0.0f;
#pragma unroll
    for (int k = 0; k < 8; k++) {
        const int idx = lane + 32 * k;
        const float ex = exp2f(fmaf(v[k].x, L2E, -mb));
        const float ey = exp2f(fmaf(v[k].y, L2E, -mb));
        const float ez = exp2f(fmaf(v[k].z, L2E, -mb));
        const float ew = exp2f(fmaf(v[k].w, L2E, -mb));
        __half2 h0 = __floats2half2_rn(ex, ey);
        __half2 h1 = __floats2half2_rn(ez, ew);
        uint2 u;
        u.x = *(const unsigned*)&h0;
        u.y = *(const unsigned*)&h1;
        pg[idx] = u;
        sp[idx] = u;
        s += (ex + ey) + (ez + ew);
    }
#pragma unroll
    for (int o = 16; o; o >>= 1)
        s += __shfl_xor_sync(0xffffffffu, s, o);
    const float r = __fdividef(1.0f, s);
    if (lane == 0) s_rh[warp] = __half2half2(__float2half_rn(r));
    __syncthreads();

    __half2 iv[RPC];
#pragma unroll
    for (int i = 0; i < RPC; i++) iv[i] = s_rh[i];

    const __half2* sp2 = (const __half2*)s_P;
    __half2 acc = __float2half2_rn(0.0f);
#pragma unroll
    for (int i = 0; i < RPC; i++)
        acc = __hfma2(sp2[i * 512 + tid], iv[i], acc);
    ((float2*)s_c)[tid] = __half22float2(acc);
    __syncthreads();

    if (tid == 0) bulk_reduce_add_4k(&d_colacc[1][b << 10], s_c);
}

// ---------------------------------------------------------------------------
// Sinkhorn iteration k (k = 1..19). 64 CTAs/batch, 16 rows each.
//   c_j = 1/colacc[k][j] -> smem
//   r_i = 1/sum_j P_ij c_j            (warp/row, fp32; P staged to smem)
//   colacc[k+1]_j += sum_i P_ij r_i   (fp16 HFMA2 for k<19, fp32 for k=19)
__global__ __launch_bounds__(512, 3)
void iter_kernel(int k) {
    extern __shared__ float smem[];
    __half*  s_P  = (__half*)smem;                 // RPC*NN halfs
    float*   s_c  = smem + RPC * NN / 2;           // NN floats
    float*   s_r  = s_c + NN;                      // RPC floats
    __half2* s_rh = (__half2*)(s_r + RPC);         // RPC half2

    const int tid  = threadIdx.x;
    const int b    = blockIdx.x >> 6;
    const int cib  = blockIdx.x & 63;
    const int warp = tid >> 5, lane = tid & 31;
    const bool last = (k == ITERS - 1);

    {
        const float* br = &d_colacc[k][b << 10];
        s_c[tid]       = __fdividef(1.0f, br[tid]);
        s_c[tid + 512] = __fdividef(1.0f, br[tid + 512]);
    }
    __syncthreads();

    const int row = (b << 10) + cib * RPC + warp;
    const uint2*  pr  = (const uint2*)(d_P + (size_t)row * NN);
    uint2*        spr = (uint2*)(s_P + warp * NN);
    const float4* c4  = (const float4*)s_c;

    // ---- phase A: warp per row, fp32 ----
    float s = 0.0f;
#pragma unroll
    for (int kk = 0; kk < 8; kk++) {
        const int idx = lane + 32 * kk;
        const uint2 pv = __ldcg(&pr[idx]);
        spr[idx] = pv;
        const float2 f0 = __half22float2(*(const __half2*)&pv.x);
        const float2 f1 = __half22float2(*(const __half2*)&pv.y);
        const float4 cv = c4[idx];
        s = fmaf(f0.x, cv.x, s);
        s = fmaf(f0.y, cv.y, s);
        s = fmaf(f1.x, cv.z, s);
        s = fmaf(f1.y, cv.w, s);
    }
#pragma unroll
    for (int o = 16; o; o >>= 1)
        s += __shfl_xor_sync(0xffffffffu, s, o);
    const float r = __fdividef(1.0f, s);
    if (lane == 0) {
        s_r[warp]  = r;
        s_rh[warp] = __half2half2(__float2half_rn(r));
        if (last) d_r[row] = r;                   // only last r feeds final
    }
    __syncthreads();

    // ---- phase B ----
    if (!last) {
        // fp16 HFMA2: 16-term partials; error self-corrected by later iters.
        __half2 iv[RPC];
#pragma unroll
        for (int i = 0; i < RPC; i++) iv[i] = s_rh[i];

        const __half2* sp2 = (const __half2*)s_P;
        __half2 acc = __float2half2_rn(0.0f);
#pragma unroll
        for (int i = 0; i < RPC; i++)
            acc = __hfma2(sp2[i * 512 + tid], iv[i], acc);
        ((float2*)s_c)[tid] = __half22float2(acc);
    } else {
        // fp32: this colacc normalizes the output directly.
        float iv[RPC];
#pragma unroll
        for (int i = 0; i < RPC; i++) iv[i] = s_r[i];

        const __half2* sp2 = (const __half2*)s_P;
        float cx = 0.0f, cy = 0.0f;
#pragma unroll
        for (int i = 0; i < RPC; i++) {
            const float2 f = __half22float2(sp2[i * 512 + tid]);
            cx = fmaf(f.x, iv[i], cx);
            cy = fmaf(f.y, iv[i], cy);
        }
        ((float2*)s_c)[tid] = make_float2(cx, cy);
    }
    __syncthreads();

    if (tid == 0) bulk_reduce_add_4k(&d_colacc[k + 1][b << 10], s_c);
}

// ---------------------------------------------------------------------------
// Final: out_ij = P_ij * r_i * c_j with c_j = 1/colacc[ITERS][j].
// P read from (hot) L2 in fp16 — no exp2, no g re-read. Warp per row.
__global__ __launch_bounds__(256) void final_kernel(float* __restrict__ out) {
    __shared__ float s_ci[NN];
    const int row0 = blockIdx.x * 8;
    const int b    = row0 >> 10;

    for (int t = threadIdx.x; t < NN; t += 256)
        s_ci[t] = __fdividef(1.0f, d_colacc[ITERS][(b << 10) + t]);
    __syncthreads();

    const int warp = threadIdx.x >> 5, lane = threadIdx.x & 31;
    const int row  = row0 + warp;
    const float rv = d_r[row];

    const uint2*  pr  = (const uint2*)(d_P + (size_t)row * NN);
    const float4* ci4 = (const float4*)s_ci;
    float4*       orw = (float4*)(out + (size_t)row * NN);

#pragma unroll
    for (int k = 0; k < 8; k++) {
        const int idx = lane + 32 * k;
        const uint2 pv = __ldcg(&pr[idx]);
        const float2 f0 = __half22float2(*(const __half2*)&pv.x);
        const float2 f1 = __half22float2(*(const __half2*)&pv.y);
        const float4 cv = ci4[idx];
        float4 o;
        o.x = f0.x * rv * cv.x;
        o.y = f0.y * rv * cv.y;
        o.z = f1.x * rv * cv.z;
        o.w = f1.y * rv * cv.w;
        orw[idx] = o;
    }
}

// ---------------------------------------------------------------------------
extern "C" void kernel_launch(void* const* d_in, const int* in_sizes, int n_in,
                              void* d_out, int out_size) {
    // Only the gumbel tensor matters (score projection cancels in the first
    // row normalization).
    const float* g = nullptr;
    for (int i = 0; i < n_in; i++)
        if (in_sizes[i] == NB * NN * NN) g = (const float*)d_in[i];
    float* out = (float*)d_out;

    const int SMEM_BYTES = RPC * NN * 2 + NN * 4 + RPC * 4 + RPC * 4;  // 36992
    cudaFuncSetAttribute(pre_iter0_kernel,
                         cudaFuncAttributeMaxDynamicSharedMemorySize, SMEM_BYTES);
    cudaFuncSetAttribute(iter_kernel,
                         cudaFuncAttributeMaxDynamicSharedMemorySize, SMEM_BYTES);

    init_kernel<<<ITERS * NB * NN / 512, 512>>>();             // zero buf[1..20]
    pre_iter0_kernel<<<NB * (NN / RPC), 512, SMEM_BYTES>>>(g); // P + iter 0

    for (int it = 1; it < ITERS; it++)
        iter_kernel<<<NB * (NN / RPC), 512, SMEM_BYTES>>>(it);

    final_kernel<<<NB * NN / 8, 256>>>(out);
}

// round 14
// speedup vs baseline: 1.2860x; 1.1268x over previous
#include <cuda_runtime.h>
#include <cuda_fp16.h>
#include <math.h>

#define NB 32
#define NN 1024
#define L2E 1.4426950408889634f
#define RPC 16                   // rows per CTA
#define ITERS 20

// Static scratch (no allocation allowed). d_P = 64 MB fp16, L2-resident.
__device__ __half d_P[(size_t)NB * NN * NN];
__device__ float  d_r[NB * NN];               // last-iteration row scalings
// Rotating column accumulators: iter k reads buf[k] (c=1/buf[k]), TMA-reduces
// into buf[k+1]. buf[1..ITERS] zeroed once per launch.
__device__ float  d_colacc[ITERS + 1][NB * NN];

// ---------------------------------------------------------------------------
__device__ __forceinline__ unsigned smem_u32(const void* p) {
    return (unsigned)__cvta_generic_to_shared(p);
}

// One 4 KB smem->global add-reduction via the TMA engine (replaces 1024
// per-thread atomics). Caller guarantees smem partials are complete.
__device__ __forceinline__ void bulk_reduce_add_4k(float* gdst, const float* ssrc) {
    asm volatile("fence.proxy.async.shared::cta;" ::: "memory");
    asm volatile(
        "cp.reduce.async.bulk.global.shared::cta.bulk_group.add.f32 [%0], [%1], %2;"
        :: "l"(gdst), "r"(smem_u32(ssrc)), "r"(NN * 4) : "memory");
    asm volatile("cp.async.bulk.commit_group;" ::: "memory");
    asm volatile("cp.async.bulk.wait_group 0;" ::: "memory");
}

// ---------------------------------------------------------------------------
// Zero buf[1..ITERS].
__global__ __launch_bounds__(512) void init_kernel() {
    ((float*)&d_colacc[1][0])[blockIdx.x * 512 + threadIdx.x] = 0.0f;
}

// ---------------------------------------------------------------------------
// Fused precompute + iteration 0. 64 CTAs/batch, 16 rows each (warp/row).
//   P_ij = exp2(g*L2E - M_i)  -> gmem (fp16) and smem tile
//   r^1_i = 1/sum_j P_ij
//   colacc[1]_j += sum_i P_ij r^1_i   (fp16 HFMA2 partials, TMA bulk reduce)
__global__ __launch_bounds__(512)
void pre_iter0_kernel(const float* __restrict__ g) {
    extern __shared__ float smem[];
    __half*  s_P  = (__half*)smem;                 // RPC*NN halfs = 32 KB
    float*   s_c  = smem + RPC * NN / 2;           // NN floats (col partials)
    __half2* s_rh = (__half2*)(s_c + NN);          // RPC half2 (r broadcast)

    const int tid  = threadIdx.x;
    const int b    = blockIdx.x >> 6;
    const int cib  = blockIdx.x & 63;
    const int warp = tid >> 5, lane = tid & 31;
    const int row  = (b << 10) + cib * RPC + warp;

    const float4* gr = (const float4*)(g + (size_t)row * NN);
    float4 v[8];
    float m = -1e30f;
#pragma unroll
    for (int k = 0; k < 8; k++) {
        v[k] = gr[lane + 32 * k];
        m = fmaxf(m, fmaxf(fmaxf(v[k].x, v[k].y), fmaxf(v[k].z, v[k].w)));
    }
#pragma unroll
    for (int o = 16; o; o >>= 1)
        m = fmaxf(m, __shfl_xor_sync(0xffffffffu, m, o));
    const float mb = m * L2E;

    uint2* pg = (uint2*)(d_P + (size_t)row * NN);
    uint2* sp = (uint2*)(s_P + warp * NN);
    float  s  = 0.0f;
#pragma unroll
    for (int k = 0; k < 8; k++) {
        const int idx = lane + 32 * k;
        const float ex = exp2f(fmaf(v[k].x, L2E, -mb));
        const float ey = exp2f(fmaf(v[k].y, L2E, -mb));
        const float ez = exp2f(fmaf(v[k].z, L2E, -mb));
        const float ew = exp2f(fmaf(v[k].w, L2E, -mb));
        __half2 h0 = __floats2half2_rn(ex, ey);
        __half2 h1 = __floats2half2_rn(ez, ew);
        uint2 u;
        u.x = *(const unsigned*)&h0;
        u.y = *(const unsigned*)&h1;
        pg[idx] = u;
        sp[idx] = u;
        s += (ex + ey) + (ez + ew);
    }
#pragma unroll
    for (int o = 16; o; o >>= 1)
        s += __shfl_xor_sync(0xffffffffu, s, o);
    const float r = __fdividef(1.0f, s);
    if (lane == 0) s_rh[warp] = __half2half2(__float2half_rn(r));
    __syncthreads();

    __half2 iv[RPC];
#pragma unroll
    for (int i = 0; i < RPC; i++) iv[i] = s_rh[i];

    const __half2* sp2 = (const __half2*)s_P;
    __half2 acc = __float2half2_rn(0.0f);
#pragma unroll
    for (int i = 0; i < RPC; i++)
        acc = __hfma2(sp2[i * 512 + tid], iv[i], acc);
    ((float2*)s_c)[tid] = __half22float2(acc);
    __syncthreads();

    if (tid == 0) bulk_reduce_add_4k(&d_colacc[1][b << 10], s_c);
}

// ---------------------------------------------------------------------------
// Fast Sinkhorn iteration (k = 1..18). 64 CTAs/batch, 16 rows each.
// c staged as half2; phase A accumulates P*c with HFMA2 in 8-term chunks
// flushed to fp32; phase B pure HFMA2. Errors here are self-corrected by the
// final fp32 iteration. 4 CTAs/SM (regs<=32, smem 38.2 KB).
__global__ __launch_bounds__(512, 4)
void iter_fast_kernel(int k) {
    extern __shared__ __align__(16) char smem_raw[];
    __half*  s_P    = (__half*)smem_raw;                          // 32 KB
    __half2* s_ch   = (__half2*)(smem_raw + RPC * NN * 2);        // 2 KB
    float*   s_part = (float*)(smem_raw + RPC * NN * 2 + NN * 2); // 4 KB
    __half2* s_rh   = (__half2*)(s_part + NN);                    // RPC half2

    const int tid  = threadIdx.x;
    const int b    = blockIdx.x >> 6;
    const int cib  = blockIdx.x & 63;
    const int warp = tid >> 5, lane = tid & 31;

    {
        const float2 v = ((const float2*)&d_colacc[k][b << 10])[tid];
        s_ch[tid] = __floats2half2_rn(__fdividef(1.0f, v.x),
                                      __fdividef(1.0f, v.y));
    }
    __syncthreads();

    const int row = (b << 10) + cib * RPC + warp;
    const uint2* pr  = (const uint2*)(d_P + (size_t)row * NN);
    uint2*       spr = (uint2*)(s_P + warp * NN);
    const uint2* c2  = (const uint2*)s_ch;

    // ---- phase A: warp per row; HFMA2 chunks of 8 terms -> fp32 ----
    float   s    = 0.0f;
    __half2 hacc = __float2half2_rn(0.0f);
#pragma unroll
    for (int kk = 0; kk < 8; kk++) {
        const int idx = lane + 32 * kk;
        const uint2 pv = __ldcg(&pr[idx]);
        spr[idx] = pv;
        const uint2 cv = c2[idx];
        hacc = __hfma2(*(const __half2*)&pv.x, *(const __half2*)&cv.x, hacc);
        hacc = __hfma2(*(const __half2*)&pv.y, *(const __half2*)&cv.y, hacc);
        if (kk & 1) {
            const float2 f = __half22float2(hacc);
            s += f.x + f.y;
            hacc = __float2half2_rn(0.0f);
        }
    }
#pragma unroll
    for (int o = 16; o; o >>= 1)
        s += __shfl_xor_sync(0xffffffffu, s, o);
    if (lane == 0)
        s_rh[warp] = __half2half2(__float2half_rn(__fdividef(1.0f, s)));
    __syncthreads();

    // ---- phase B: thread owns 2 adjacent columns; pure HFMA2 ----
    __half2 iv[RPC];
#pragma unroll
    for (int i = 0; i < RPC; i++) iv[i] = s_rh[i];

    const __half2* sp2 = (const __half2*)s_P;
    __half2 acc = __float2half2_rn(0.0f);
#pragma unroll
    for (int i = 0; i < RPC; i++)
        acc = __hfma2(sp2[i * 512 + tid], iv[i], acc);
    ((float2*)s_part)[tid] = __half22float2(acc);
    __syncthreads();

    if (tid == 0) bulk_reduce_add_4k(&d_colacc[k + 1][b << 10], s_part);
}

// ---------------------------------------------------------------------------
// Last iteration (k = 19), fully fp32: its r and colacc feed the output.
__global__ __launch_bounds__(512, 3)
void iter_last_kernel() {
    extern __shared__ float smem[];
    __half* s_P = (__half*)smem;                   // RPC*NN halfs
    float*  s_c = smem + RPC * NN / 2;             // NN floats (c, then partials)
    float*  s_r = s_c + NN;                        // RPC floats

    const int k    = ITERS - 1;
    const int tid  = threadIdx.x;
    const int b    = blockIdx.x >> 6;
    const int cib  = blockIdx.x & 63;
    const int warp = tid >> 5, lane = tid & 31;

    {
        const float* br = &d_colacc[k][b << 10];
        s_c[tid]       = __fdividef(1.0f, br[tid]);
        s_c[tid + 512] = __fdividef(1.0f, br[tid + 512]);
    }
    __syncthreads();

    const int row = (b << 10) + cib * RPC + warp;
    const uint2*  pr  = (const uint2*)(d_P + (size_t)row * NN);
    uint2*        spr = (uint2*)(s_P + warp * NN);
    const float4* c4  = (const float4*)s_c;

    float s = 0.0f;
#pragma unroll
    for (int kk = 0; kk < 8; kk++) {
        const int idx = lane + 32 * kk;
        const uint2 pv = __ldcg(&pr[idx]);
        spr[idx] = pv;
        const float2 f0 = __half22float2(*(const __half2*)&pv.x);
        const float2 f1 = __half22float2(*(const __half2*)&pv.y);
        const float4 cv = c4[idx];
        s = fmaf(f0.x, cv.x, s);
        s = fmaf(f0.y, cv.y, s);
        s = fmaf(f1.x, cv.z, s);
        s = fmaf(f1.y, cv.w, s);
    }
#pragma unroll
    for (int o = 16; o; o >>= 1)
        s += __shfl_xor_sync(0xffffffffu, s, o);
    const float r = __fdividef(1.0f, s);
    if (lane == 0) {
        s_r[warp] = r;
        d_r[row]  = r;                             // feeds final_kernel
    }
    __syncthreads();

    float iv[RPC];
#pragma unroll
    for (int i = 0; i < RPC; i++) iv[i] = s_r[i];

    const __half2* sp2 = (const __half2*)s_P;
    float cx = 0.0f, cy = 0.0f;
#pragma unroll
    for (int i = 0; i < RPC; i++) {
        const float2 f = __half22float2(sp2[i * 512 + tid]);
        cx = fmaf(f.x, iv[i], cx);
        cy = fmaf(f.y, iv[i], cy);
    }
    ((float2*)s_c)[tid] = make_float2(cx, cy);
    __syncthreads();

    if (tid == 0) bulk_reduce_add_4k(&d_colacc[k + 1][b << 10], s_c);
}

// ---------------------------------------------------------------------------
// Final: out_ij = P_ij * r_i * c_j with c_j = 1/colacc[ITERS][j].
// P read from (hot) L2 in fp16 — no exp2, no g re-read. Warp per row.
__global__ __launch_bounds__(256) void final_kernel(float* __restrict__ out) {
    __shared__ float s_ci[NN];
    const int row0 = blockIdx.x * 8;
    const int b    = row0 >> 10;

    for (int t = threadIdx.x; t < NN; t += 256)
        s_ci[t] = __fdividef(1.0f, d_colacc[ITERS][(b << 10) + t]);
    __syncthreads();

    const int warp = threadIdx.x >> 5, lane = threadIdx.x & 31;
    const int row  = row0 + warp;
    const float rv = d_r[row];

    const uint2*  pr  = (const uint2*)(d_P + (size_t)row * NN);
    const float4* ci4 = (const float4*)s_ci;
    float4*       orw = (float4*)(out + (size_t)row * NN);

#pragma unroll
    for (int k = 0; k < 8; k++) {
        const int idx = lane + 32 * k;
        const uint2 pv = __ldcg(&pr[idx]);
        const float2 f0 = __half22float2(*(const __half2*)&pv.x);
        const float2 f1 = __half22float2(*(const __half2*)&pv.y);
        const float4 cv = ci4[idx];
        float4 o;
        o.x = f0.x * rv * cv.x;
        o.y = f0.y * rv * cv.y;
        o.z = f1.x * rv * cv.z;
        o.w = f1.y * rv * cv.w;
        orw[idx] = o;
    }
}

// ---------------------------------------------------------------------------
extern "C" void kernel_launch(void* const* d_in, const int* in_sizes, int n_in,
                              void* d_out, int out_size) {
    // Only the gumbel tensor matters (score projection cancels in the first
    // row normalization).
    const float* g = nullptr;
    for (int i = 0; i < n_in; i++)
        if (in_sizes[i] == NB * NN * NN) g = (const float*)d_in[i];
    float* out = (float*)d_out;

    const int PRE_SMEM  = RPC * NN * 2 + NN * 4 + RPC * 4;            // 36928
    const int FAST_SMEM = RPC * NN * 2 + NN * 2 + NN * 4 + RPC * 4;   // 38976
    const int LAST_SMEM = RPC * NN * 2 + NN * 4 + RPC * 4;            // 36928
    cudaFuncSetAttribute(pre_iter0_kernel,
                         cudaFuncAttributeMaxDynamicSharedMemorySize, PRE_SMEM);
    cudaFuncSetAttribute(iter_fast_kernel,
                         cudaFuncAttributeMaxDynamicSharedMemorySize, FAST_SMEM);
    cudaFuncSetAttribute(iter_last_kernel,
                         cudaFuncAttributeMaxDynamicSharedMemorySize, LAST_SMEM);

    const int GRID = NB * (NN / RPC);   // 2048

    init_kernel<<<ITERS * NB * NN / 512, 512>>>();         // zero buf[1..20]
    pre_iter0_kernel<<<GRID, 512, PRE_SMEM>>>(g);          // P + iter 0

    for (int it = 1; it < ITERS - 1; it++)
        iter_fast_kernel<<<GRID, 512, FAST_SMEM>>>(it);
    iter_last_kernel<<<GRID, 512, LAST_SMEM>>>();

    final_kernel<<<NB * NN / 8, 256>>>(out);
}

// round 15
// speedup vs baseline: 1.4177x; 1.1023x over previous
#include <cuda_runtime.h>
#include <cuda_fp16.h>
#include <math.h>

#define NB 32
#define NN 1024
#define L2E 1.4426950408889634f
#define RPC 16                   // rows per CTA
#define ITERS 20

// Static scratch (no allocation allowed). d_P = 64 MB fp16, L2-resident.
__device__ __half d_P[(size_t)NB * NN * NN];
__device__ float  d_r[NB * NN];               // last-iteration row scalings
// Rotating column accumulators: iter k reads buf[k] (c=1/buf[k]), TMA-reduces
// into buf[k+1]. buf[1..ITERS] zeroed once per launch.
__device__ float  d_colacc[ITERS + 1][NB * NN];

// ---------------------------------------------------------------------------
__device__ __forceinline__ unsigned smem_u32(const void* p) {
    return (unsigned)__cvta_generic_to_shared(p);
}

// One 4 KB smem->global add-reduction via the TMA engine (replaces 1024
// per-thread atomics). Caller guarantees smem partials are complete.
__device__ __forceinline__ void bulk_reduce_add_4k(float* gdst, const float* ssrc) {
    asm volatile("fence.proxy.async.shared::cta;" ::: "memory");
    asm volatile(
        "cp.reduce.async.bulk.global.shared::cta.bulk_group.add.f32 [%0], [%1], %2;"
        :: "l"(gdst), "r"(smem_u32(ssrc)), "r"(NN * 4) : "memory");
    asm volatile("cp.async.bulk.commit_group;" ::: "memory");
    asm volatile("cp.async.bulk.wait_group 0;" ::: "memory");
}

// Blocking mbarrier wait, parity phase.
__device__ __forceinline__ void mbar_wait(unsigned mbar, unsigned parity) {
    unsigned done;
    asm volatile(
        "{\n\t.reg .pred p;\n\t"
        "mbarrier.try_wait.parity.acquire.cta.shared::cta.b64 p, [%1], %2;\n\t"
        "selp.b32 %0, 1, 0, p;\n\t}"
        : "=r"(done) : "r"(mbar), "r"(parity) : "memory");
    while (!done) {
        asm volatile(
            "{\n\t.reg .pred p;\n\t"
            "mbarrier.try_wait.parity.acquire.cta.shared::cta.b64 p, [%1], %2, 0x989680;\n\t"
            "selp.b32 %0, 1, 0, p;\n\t}"
            : "=r"(done) : "r"(mbar), "r"(parity) : "memory");
    }
}

// ---------------------------------------------------------------------------
// Zero buf[1..ITERS].
__global__ __launch_bounds__(512) void init_kernel() {
    ((float*)&d_colacc[1][0])[blockIdx.x * 512 + threadIdx.x] = 0.0f;
}

// ---------------------------------------------------------------------------
// Fused precompute + iteration 0. 64 CTAs/batch, 16 rows each (warp/row).
//   P_ij = exp2(g*L2E - M_i)  -> gmem (fp16) and smem tile
//   r^1_i = 1/sum_j P_ij
//   colacc[1]_j += sum_i P_ij r^1_i   (fp16 HFMA2 partials, TMA bulk reduce)
__global__ __launch_bounds__(512)
void pre_iter0_kernel(const float* __restrict__ g) {
    extern __shared__ float smem[];
    __half*  s_P  = (__half*)smem;                 // RPC*NN halfs = 32 KB
    float*   s_c  = smem + RPC * NN / 2;           // NN floats (col partials)
    __half2* s_rh = (__half2*)(s_c + NN);          // RPC half2 (r broadcast)

    const int tid  = threadIdx.x;
    const int b    = blockIdx.x >> 6;
    const int cib  = blockIdx.x & 63;
    const int warp = tid >> 5, lane = tid & 31;
    const int row  = (b << 10) + cib * RPC + warp;

    const float4* gr = (const float4*)(g + (size_t)row * NN);
    float4 v[8];
    float m = -1e30f;
#pragma unroll
    for (int k = 0; k < 8; k++) {
        v[k] = gr[lane + 32 * k];
        m = fmaxf(m, fmaxf(fmaxf(v[k].x, v[k].y), fmaxf(v[k].z, v[k].w)));
    }
#pragma unroll
    for (int o = 16; o; o >>= 1)
        m = fmaxf(m, __shfl_xor_sync(0xffffffffu, m, o));
    const float mb = m * L2E;

    uint2* pg = (uint2*)(d_P + (size_t)row * NN);
    uint2* sp = (uint2*)(s_P + warp * NN);
    float  s  = 0.0f;
#pragma unroll
    for (int k = 0; k < 8; k++) {
        const int idx = lane + 32 * k;
        const float ex = exp2f(fmaf(v[k].x, L2E, -mb));
        const float ey = exp2f(fmaf(v[k].y, L2E, -mb));
        const float ez = exp2f(fmaf(v[k].z, L2E, -mb));
        const float ew = exp2f(fmaf(v[k].w, L2E, -mb));
        __half2 h0 = __floats2half2_rn(ex, ey);
        __half2 h1 = __floats2half2_rn(ez, ew);
        uint2 u;
        u.x = *(const unsigned*)&h0;
        u.y = *(const unsigned*)&h1;
        pg[idx] = u;
        sp[idx] = u;
        s += (ex + ey) + (ez + ew);
    }
#pragma unroll
    for (int o = 16; o; o >>= 1)
        s += __shfl_xor_sync(0xffffffffu, s, o);
    const float r = __fdividef(1.0f, s);
    if (lane == 0) s_rh[warp] = __half2half2(__float2half_rn(r));
    __syncthreads();

    __half2 iv[RPC];
#pragma unroll
    for (int i = 0; i < RPC; i++) iv[i] = s_rh[i];

    const __half2* sp2 = (const __half2*)s_P;
    __half2 acc = __float2half2_rn(0.0f);
#pragma unroll
    for (int i = 0; i < RPC; i++)
        acc = __hfma2(sp2[i * 512 + tid], iv[i], acc);
    ((float2*)s_c)[tid] = __half22float2(acc);
    __syncthreads();

    if (tid == 0) bulk_reduce_add_4k(&d_colacc[1][b << 10], s_c);
}

// ---------------------------------------------------------------------------
// Fast Sinkhorn iteration (k = 1..18). 64 CTAs/batch, 16 rows each.
// P tile (contiguous 32 KB) fetched by ONE cp.async.bulk (TMA engine) while
// all threads stage c = 1/colacc as half2. Phase A: warp/row, LDS.128 +
// HFMA2 chunks flushed to fp32. Phase B: pure HFMA2 column partials.
// Errors self-corrected by the final fp32 iteration. 4 CTAs/SM.
__global__ __launch_bounds__(512, 4)
void iter_fast_kernel(int k) {
    extern __shared__ __align__(128) char smem_raw[];
    __half*  s_P    = (__half*)smem_raw;                          // 32 KB
    __half2* s_ch   = (__half2*)(smem_raw + RPC * NN * 2);        // 2 KB
    float*   s_part = (float*)(smem_raw + RPC * NN * 2 + NN * 2); // 4 KB
    __half2* s_rh   = (__half2*)(s_part + NN);                    // 64 B
    unsigned long long* s_mbar = (unsigned long long*)(s_rh + RPC);

    const int tid  = threadIdx.x;
    const int b    = blockIdx.x >> 6;
    const int cib  = blockIdx.x & 63;
    const int warp = tid >> 5, lane = tid & 31;
    const unsigned mbar = smem_u32(s_mbar);

    if (tid == 0)
        asm volatile("mbarrier.init.shared.b64 [%0], 1;" :: "r"(mbar) : "memory");
    __syncthreads();

    if (tid == 0) {
        const __half* src = d_P + ((size_t)((b << 10) + cib * RPC)) * NN;
        asm volatile(
            "mbarrier.arrive.expect_tx.shared.b64 _, [%0], %1;"
            :: "r"(mbar), "r"(RPC * NN * 2) : "memory");
        asm volatile(
            "cp.async.bulk.shared::cta.global.mbarrier::complete_tx::bytes "
            "[%0], [%1], %2, [%3];"
            :: "r"(smem_u32(s_P)), "l"(src), "r"(RPC * NN * 2), "r"(mbar)
            : "memory");
    }

    // stage c (overlaps the bulk copy)
    {
        const float2 v = ((const float2*)&d_colacc[k][b << 10])[tid];
        s_ch[tid] = __floats2half2_rn(__fdividef(1.0f, v.x),
                                      __fdividef(1.0f, v.y));
    }
    __syncthreads();            // c ready
    mbar_wait(mbar, 0);         // P tile ready

    // ---- phase A: warp per row; LDS.128 + HFMA2 chunks -> fp32 ----
    const uint4* p4 = (const uint4*)(s_P + warp * NN);
    const uint4* c4 = (const uint4*)s_ch;

    float s = 0.0f;
#pragma unroll
    for (int kk = 0; kk < 4; kk++) {
        const int idx = lane + 32 * kk;          // uint4 slot (8 halves)
        const uint4 pv = p4[idx];
        const uint4 cv = c4[idx];
        __half2 hacc = __float2half2_rn(0.0f);
        hacc = __hfma2(*(const __half2*)&pv.x, *(const __half2*)&cv.x, hacc);
        hacc = __hfma2(*(const __half2*)&pv.y, *(const __half2*)&cv.y, hacc);
        hacc = __hfma2(*(const __half2*)&pv.z, *(const __half2*)&cv.z, hacc);
        hacc = __hfma2(*(const __half2*)&pv.w, *(const __half2*)&cv.w, hacc);
        const float2 f = __half22float2(hacc);
        s += f.x + f.y;
    }
#pragma unroll
    for (int o = 16; o; o >>= 1)
        s += __shfl_xor_sync(0xffffffffu, s, o);
    if (lane == 0)
        s_rh[warp] = __half2half2(__float2half_rn(__fdividef(1.0f, s)));
    __syncthreads();

    // ---- phase B: thread owns 2 adjacent columns; pure HFMA2 ----
    __half2 iv[RPC];
#pragma unroll
    for (int i = 0; i < RPC; i++) iv[i] = s_rh[i];

    const __half2* sp2 = (const __half2*)s_P;
    __half2 acc = __float2half2_rn(0.0f);
#pragma unroll
    for (int i = 0; i < RPC; i++)
        acc = __hfma2(sp2[i * 512 + tid], iv[i], acc);
    ((float2*)s_part)[tid] = __half22float2(acc);
    __syncthreads();

    if (tid == 0) bulk_reduce_add_4k(&d_colacc[k + 1][b << 10], s_part);
}

// ---------------------------------------------------------------------------
// Last iteration (k = 19), fully fp32: its r and colacc feed the output.
__global__ __launch_bounds__(512, 3)
void iter_last_kernel() {
    extern __shared__ float smem[];
    __half* s_P = (__half*)smem;                   // RPC*NN halfs
    float*  s_c = smem + RPC * NN / 2;             // NN floats (c, then partials)
    float*  s_r = s_c + NN;                        // RPC floats

    const int k    = ITERS - 1;
    const int tid  = threadIdx.x;
    const int b    = blockIdx.x >> 6;
    const int cib  = blockIdx.x & 63;
    const int warp = tid >> 5, lane = tid & 31;

    {
        const float* br = &d_colacc[k][b << 10];
        s_c[tid]       = __fdividef(1.0f, br[tid]);
        s_c[tid + 512] = __fdividef(1.0f, br[tid + 512]);
    }
    __syncthreads();

    const int row = (b << 10) + cib * RPC + warp;
    const uint2*  pr  = (const uint2*)(d_P + (size_t)row * NN);
    uint2*        spr = (uint2*)(s_P + warp * NN);
    const float4* c4  = (const float4*)s_c;

    float s = 0.0f;
#pragma unroll
    for (int kk = 0; kk < 8; kk++) {
        const int idx = lane + 32 * kk;
        const uint2 pv = __ldcg(&pr[idx]);
        spr[idx] = pv;
        const float2 f0 = __half22float2(*(const __half2*)&pv.x);
        const float2 f1 = __half22float2(*(const __half2*)&pv.y);
        const float4 cv = c4[idx];
        s = fmaf(f0.x, cv.x, s);
        s = fmaf(f0.y, cv.y, s);
        s = fmaf(f1.x, cv.z, s);
        s = fmaf(f1.y, cv.w, s);
    }
#pragma unroll
    for (int o = 16; o; o >>= 1)
        s += __shfl_xor_sync(0xffffffffu, s, o);
    const float r = __fdividef(1.0f, s);
    if (lane == 0) {
        s_r[warp] = r;
        d_r[row]  = r;                             // feeds final_kernel
    }
    __syncthreads();

    float iv[RPC];
#pragma unroll
    for (int i = 0; i < RPC; i++) iv[i] = s_r[i];

    const __half2* sp2 = (const __half2*)s_P;
    float cx = 0.0f, cy = 0.0f;
#pragma unroll
    for (int i = 0; i < RPC; i++) {
        const float2 f = __half22float2(sp2[i * 512 + tid]);
        cx = fmaf(f.x, iv[i], cx);
        cy = fmaf(f.y, iv[i], cy);
    }
    ((float2*)s_c)[tid] = make_float2(cx, cy);
    __syncthreads();

    if (tid == 0) bulk_reduce_add_4k(&d_colacc[k + 1][b << 10], s_c);
}

// ---------------------------------------------------------------------------
// Final: out_ij = P_ij * r_i * c_j with c_j = 1/colacc[ITERS][j].
// P read from (hot) L2 in fp16 — no exp2, no g re-read. Warp per row.
__global__ __launch_bounds__(256) void final_kernel(float* __restrict__ out) {
    __shared__ float s_ci[NN];
    const int row0 = blockIdx.x * 8;
    const int b    = row0 >> 10;

    for (int t = threadIdx.x; t < NN; t += 256)
        s_ci[t] = __fdividef(1.0f, d_colacc[ITERS][(b << 10) + t]);
    __syncthreads();

    const int warp = threadIdx.x >> 5, lane = threadIdx.x & 31;
    const int row  = row0 + warp;
    const float rv = d_r[row];

    const uint2*  pr  = (const uint2*)(d_P + (size_t)row * NN);
    const float4* ci4 = (const float4*)s_ci;
    float4*       orw = (float4*)(out + (size_t)row * NN);

#pragma unroll
    for (int k = 0; k < 8; k++) {
        const int idx = lane + 32 * k;
        const uint2 pv = __ldcg(&pr[idx]);
        const float2 f0 = __half22float2(*(const __half2*)&pv.x);
        const float2 f1 = __half22float2(*(const __half2*)&pv.y);
        const float4 cv = ci4[idx];
        float4 o;
        o.x = f0.x * rv * cv.x;
        o.y = f0.y * rv * cv.y;
        o.z = f1.x * rv * cv.z;
        o.w = f1.y * rv * cv.w;
        orw[idx] = o;
    }
}

// ---------------------------------------------------------------------------
extern "C" void kernel_launch(void* const* d_in, const int* in_sizes, int n_in,
                              void* d_out, int out_size) {
    // Only the gumbel tensor matters (score projection cancels in the first
    // row normalization).
    const float* g = nullptr;
    for (int i = 0; i < n_in; i++)
        if (in_sizes[i] == NB * NN * NN) g = (const float*)d_in[i];
    float* out = (float*)d_out;

    const int PRE_SMEM  = RPC * NN * 2 + NN * 4 + RPC * 4;                 // 36928
    const int FAST_SMEM = RPC * NN * 2 + NN * 2 + NN * 4 + RPC * 4 + 16;   // 38992
    const int LAST_SMEM = RPC * NN * 2 + NN * 4 + RPC * 4;                 // 36928
    cudaFuncSetAttribute(pre_iter0_kernel,
                         cudaFuncAttributeMaxDynamicSharedMemorySize, PRE_SMEM);
    cudaFuncSetAttribute(iter_fast_kernel,
                         cudaFuncAttributeMaxDynamicSharedMemorySize, FAST_SMEM);
    cudaFuncSetAttribute(iter_last_kernel,
                         cudaFuncAttributeMaxDynamicSharedMemorySize, LAST_SMEM);

    const int GRID = NB * (NN / RPC);   // 2048

    init_kernel<<<ITERS * NB * NN / 512, 512>>>();         // zero buf[1..20]
    pre_iter0_kernel<<<GRID, 512, PRE_SMEM>>>(g);          // P + iter 0

    for (int it = 1; it < ITERS - 1; it++)
        iter_fast_kernel<<<GRID, 512, FAST_SMEM>>>(it);
    iter_last_kernel<<<GRID, 512, LAST_SMEM>>>();

    final_kernel<<<NB * NN / 8, 256>>>(out);
}

// round 16
// speedup vs baseline: 1.4957x; 1.0551x over previous
#include <cuda_runtime.h>
#include <cuda_fp16.h>
#include <math.h>

#define NB 32
#define NN 1024
#define L2E 1.4426950408889634f
#define RPC 16                   // rows per tile
#define ITERS 20

// Static scratch (no allocation allowed). d_P = 64 MB fp16, L2-resident.
__device__ __half d_P[(size_t)NB * NN * NN];
__device__ float  d_r[NB * NN];               // last-iteration row scalings
// Rotating column accumulators: iter k reads buf[k] (c=1/buf[k]), TMA-reduces
// into buf[k+1]. buf[1..ITERS] zeroed once per launch.
__device__ float  d_colacc[ITERS + 1][NB * NN];

// ---------------------------------------------------------------------------
__device__ __forceinline__ unsigned smem_u32(const void* p) {
    return (unsigned)__cvta_generic_to_shared(p);
}

// One 4 KB smem->global add-reduction via the TMA engine.
__device__ __forceinline__ void bulk_reduce_add_4k(float* gdst, const float* ssrc) {
    asm volatile("fence.proxy.async.shared::cta;" ::: "memory");
    asm volatile(
        "cp.reduce.async.bulk.global.shared::cta.bulk_group.add.f32 [%0], [%1], %2;"
        :: "l"(gdst), "r"(smem_u32(ssrc)), "r"(NN * 4) : "memory");
    asm volatile("cp.async.bulk.commit_group;" ::: "memory");
    asm volatile("cp.async.bulk.wait_group 0;" ::: "memory");
}

// Blocking mbarrier wait, parity phase.
__device__ __forceinline__ void mbar_wait(unsigned mbar, unsigned parity) {
    unsigned done;
    asm volatile(
        "{\n\t.reg .pred p;\n\t"
        "mbarrier.try_wait.parity.acquire.cta.shared::cta.b64 p, [%1], %2;\n\t"
        "selp.b32 %0, 1, 0, p;\n\t}"
        : "=r"(done) : "r"(mbar), "r"(parity) : "memory");
    while (!done) {
        asm volatile(
            "{\n\t.reg .pred p;\n\t"
            "mbarrier.try_wait.parity.acquire.cta.shared::cta.b64 p, [%1], %2, 0x989680;\n\t"
            "selp.b32 %0, 1, 0, p;\n\t}"
            : "=r"(done) : "r"(mbar), "r"(parity) : "memory");
    }
}

__device__ __forceinline__ void tma_tile_load(unsigned sdst, const __half* src,
                                              unsigned mbar) {
    asm volatile(
        "mbarrier.arrive.expect_tx.shared.b64 _, [%0], %1;"
        :: "r"(mbar), "r"(RPC * NN * 2) : "memory");
    asm volatile(
        "cp.async.bulk.shared::cta.global.mbarrier::complete_tx::bytes "
        "[%0], [%1], %2, [%3];"
        :: "r"(sdst), "l"(src), "r"(RPC * NN * 2), "r"(mbar) : "memory");
}

// ---------------------------------------------------------------------------
// Zero buf[1..ITERS].
__global__ __launch_bounds__(512) void init_kernel() {
    ((float*)&d_colacc[1][0])[blockIdx.x * 512 + threadIdx.x] = 0.0f;
}

// ---------------------------------------------------------------------------
// Fused precompute + iteration 0. 64 CTAs/batch, 16 rows each (warp/row).
//   P_ij = exp2(g*L2E - M_i)  -> gmem (fp16) and smem tile
//   r^1_i = 1/sum_j P_ij
//   colacc[1]_j += sum_i P_ij r^1_i   (fp16 HFMA2 partials, TMA bulk reduce)
__global__ __launch_bounds__(512)
void pre_iter0_kernel(const float* __restrict__ g) {
    extern __shared__ float smem[];
    __half*  s_P  = (__half*)smem;                 // RPC*NN halfs = 32 KB
    float*   s_c  = smem + RPC * NN / 2;           // NN floats (col partials)
    __half2* s_rh = (__half2*)(s_c + NN);          // RPC half2 (r broadcast)

    const int tid  = threadIdx.x;
    const int b    = blockIdx.x >> 6;
    const int cib  = blockIdx.x & 63;
    const int warp = tid >> 5, lane = tid & 31;
    const int row  = (b << 10) + cib * RPC + warp;

    const float4* gr = (const float4*)(g + (size_t)row * NN);
    float4 v[8];
    float m = -1e30f;
#pragma unroll
    for (int k = 0; k < 8; k++) {
        v[k] = gr[lane + 32 * k];
        m = fmaxf(m, fmaxf(fmaxf(v[k].x, v[k].y), fmaxf(v[k].z, v[k].w)));
    }
#pragma unroll
    for (int o = 16; o; o >>= 1)
        m = fmaxf(m, __shfl_xor_sync(0xffffffffu, m, o));
    const float mb = m * L2E;

    uint2* pg = (uint2*)(d_P + (size_t)row * NN);
    uint2* sp = (uint2*)(s_P + warp * NN);
    float  s  = 0.0f;
#pragma unroll
    for (int k = 0; k < 8; k++) {
        const int idx = lane + 32 * k;
        const float ex = exp2f(fmaf(v[k].x, L2E, -mb));
        const float ey = exp2f(fmaf(v[k].y, L2E, -mb));
        const float ez = exp2f(fmaf(v[k].z, L2E, -mb));
        const float ew = exp2f(fmaf(v[k].w, L2E, -mb));
        __half2 h0 = __floats2half2_rn(ex, ey);
        __half2 h1 = __floats2half2_rn(ez, ew);
        uint2 u;
        u.x = *(const unsigned*)&h0;
        u.y = *(const unsigned*)&h1;
        pg[idx] = u;
        sp[idx] = u;
        s += (ex + ey) + (ez + ew);
    }
#pragma unroll
    for (int o = 16; o; o >>= 1)
        s += __shfl_xor_sync(0xffffffffu, s, o);
    const float r = __fdividef(1.0f, s);
    if (lane == 0) s_rh[warp] = __half2half2(__float2half_rn(r));
    __syncthreads();

    __half2 iv[RPC];
#pragma unroll
    for (int i = 0; i < RPC; i++) iv[i] = s_rh[i];

    const __half2* sp2 = (const __half2*)s_P;
    __half2 acc = __float2half2_rn(0.0f);
#pragma unroll
    for (int i = 0; i < RPC; i++)
        acc = __hfma2(sp2[i * 512 + tid], iv[i], acc);
    ((float2*)s_c)[tid] = __half22float2(acc);
    __syncthreads();

    if (tid == 0) bulk_reduce_add_4k(&d_colacc[1][b << 10], s_c);
}

// ---------------------------------------------------------------------------
// Phase A helper: warp-per-row sum of P*c over one tile row (LDS.128 + HFMA2
// chunks of 8 flushed to fp32).
__device__ __forceinline__ float rowsum_h2(const __half* tile_row,
                                           const __half2* s_ch, int lane) {
    const uint4* p4 = (const uint4*)tile_row;
    const uint4* c4 = (const uint4*)s_ch;
    float s = 0.0f;
#pragma unroll
    for (int kk = 0; kk < 4; kk++) {
        const int idx = lane + 32 * kk;
        const uint4 pv = p4[idx];
        const uint4 cv = c4[idx];
        __half2 hacc = __float2half2_rn(0.0f);
        hacc = __hfma2(*(const __half2*)&pv.x, *(const __half2*)&cv.x, hacc);
        hacc = __hfma2(*(const __half2*)&pv.y, *(const __half2*)&cv.y, hacc);
        hacc = __hfma2(*(const __half2*)&pv.z, *(const __half2*)&cv.z, hacc);
        hacc = __hfma2(*(const __half2*)&pv.w, *(const __half2*)&cv.w, hacc);
        const float2 f = __half22float2(hacc);
        s += f.x + f.y;
    }
#pragma unroll
    for (int o = 16; o; o >>= 1)
        s += __shfl_xor_sync(0xffffffffu, s, o);
    return s;
}

// Phase B helper: 16-term fp16 column partial for this thread's 2 columns,
// folded into fp32 accumulators.
__device__ __forceinline__ void colpart_h2(const __half* tile, const __half2* rh,
                                           int tid, float& cx, float& cy) {
    __half2 iv[RPC];
#pragma unroll
    for (int i = 0; i < RPC; i++) iv[i] = rh[i];
    const __half2* sp2 = (const __half2*)tile;
    __half2 acc = __float2half2_rn(0.0f);
#pragma unroll
    for (int i = 0; i < RPC; i++)
        acc = __hfma2(sp2[i * 512 + tid], iv[i], acc);
    const float2 f = __half22float2(acc);
    cx += f.x;
    cy += f.y;
}

// ---------------------------------------------------------------------------
// Fast Sinkhorn iteration (k = 1..18). 32 CTAs/batch, TWO 16-row tiles each.
// Both tiles' TMA copies issued up-front (tile1 streams while tile0 computes).
// Column partials accumulate in registers across tiles -> ONE bulk reduce per
// CTA (halves REDG traffic). 3 CTAs/SM (smem ~71.8 KB).
__global__ __launch_bounds__(512, 3)
void iter_fast_kernel(int k) {
    extern __shared__ __align__(128) char smem_raw[];
    __half*  s_P0   = (__half*)smem_raw;                          // 32 KB
    __half*  s_P1   = (__half*)(smem_raw + RPC * NN * 2);         // 32 KB
    __half2* s_ch   = (__half2*)(smem_raw + 2 * RPC * NN * 2);    // 2 KB
    float*   s_part = (float*)((char*)s_ch + NN * 2);             // 4 KB
    __half2* s_rh0  = (__half2*)(s_part + NN);                    // 32 B
    __half2* s_rh1  = s_rh0 + RPC;                                // 32 B
    unsigned long long* s_mbar = (unsigned long long*)(s_rh1 + RPC);

    const int tid  = threadIdx.x;
    const int b    = blockIdx.x >> 5;            // 32 CTAs per batch
    const int cib  = blockIdx.x & 31;
    const int warp = tid >> 5, lane = tid & 31;
    const unsigned mbar0 = smem_u32(s_mbar);
    const unsigned mbar1 = smem_u32(s_mbar + 1);

    if (tid == 0) {
        asm volatile("mbarrier.init.shared.b64 [%0], 1;" :: "r"(mbar0) : "memory");
        asm volatile("mbarrier.init.shared.b64 [%0], 1;" :: "r"(mbar1) : "memory");
    }
    __syncthreads();

    if (tid == 0) {
        const __half* src = d_P + ((size_t)((b << 10) + cib * 2 * RPC)) * NN;
        tma_tile_load(smem_u32(s_P0), src, mbar0);
        tma_tile_load(smem_u32(s_P1), src + (size_t)RPC * NN, mbar1);
    }

    // stage c (overlaps both bulk copies)
    {
        const float2 v = ((const float2*)&d_colacc[k][b << 10])[tid];
        s_ch[tid] = __floats2half2_rn(__fdividef(1.0f, v.x),
                                      __fdividef(1.0f, v.y));
    }
    __syncthreads();            // c ready
    mbar_wait(mbar0, 0);        // tile0 ready (tile1 still streaming)

    // ---- tile0 phase A ----
    float s0 = rowsum_h2(s_P0 + warp * NN, s_ch, lane);
    if (lane == 0)
        s_rh0[warp] = __half2half2(__float2half_rn(__fdividef(1.0f, s0)));
    __syncthreads();

    // ---- tile0 phase B (into registers) ----
    float cx = 0.0f, cy = 0.0f;
    colpart_h2(s_P0, s_rh0, tid, cx, cy);

    // ---- tile1 phase A ----
    mbar_wait(mbar1, 0);
    float s1 = rowsum_h2(s_P1 + warp * NN, s_ch, lane);
    if (lane == 0)
        s_rh1[warp] = __half2half2(__float2half_rn(__fdividef(1.0f, s1)));
    __syncthreads();

    // ---- tile1 phase B ----
    colpart_h2(s_P1, s_rh1, tid, cx, cy);

    ((float2*)s_part)[tid] = make_float2(cx, cy);
    __syncthreads();

    if (tid == 0) bulk_reduce_add_4k(&d_colacc[k + 1][b << 10], s_part);
}

// ---------------------------------------------------------------------------
// Last iteration (k = 19), fully fp32: its r and colacc feed the output.
__global__ __launch_bounds__(512, 3)
void iter_last_kernel() {
    extern __shared__ float smem[];
    __half* s_P = (__half*)smem;                   // RPC*NN halfs
    float*  s_c = smem + RPC * NN / 2;             // NN floats (c, then partials)
    float*  s_r = s_c + NN;                        // RPC floats

    const int k    = ITERS - 1;
    const int tid  = threadIdx.x;
    const int b    = blockIdx.x >> 6;
    const int cib  = blockIdx.x & 63;
    const int warp = tid >> 5, lane = tid & 31;

    {
        const float* br = &d_colacc[k][b << 10];
        s_c[tid]       = __fdividef(1.0f, br[tid]);
        s_c[tid + 512] = __fdividef(1.0f, br[tid + 512]);
    }
    __syncthreads();

    const int row = (b << 10) + cib * RPC + warp;
    const uint2*  pr  = (const uint2*)(d_P + (size_t)row * NN);
    uint2*        spr = (uint2*)(s_P + warp * NN);
    const float4* c4  = (const float4*)s_c;

    float s = 0.0f;
#pragma unroll
    for (int kk = 0; kk < 8; kk++) {
        const int idx = lane + 32 * kk;
        const uint2 pv = __ldcg(&pr[idx]);
        spr[idx] = pv;
        const float2 f0 = __half22float2(*(const __half2*)&pv.x);
        const float2 f1 = __half22float2(*(const __half2*)&pv.y);
        const float4 cv = c4[idx];
        s = fmaf(f0.x, cv.x, s);
        s = fmaf(f0.y, cv.y, s);
        s = fmaf(f1.x, cv.z, s);
        s = fmaf(f1.y, cv.w, s);
    }
#pragma unroll
    for (int o = 16; o; o >>= 1)
        s += __shfl_xor_sync(0xffffffffu, s, o);
    const float r = __fdividef(1.0f, s);
    if (lane == 0) {
        s_r[warp] = r;
        d_r[row]  = r;                             // feeds final_kernel
    }
    __syncthreads();

    float iv[RPC];
#pragma unroll
    for (int i = 0; i < RPC; i++) iv[i] = s_r[i];

    const __half2* sp2 = (const __half2*)s_P;
    float cx = 0.0f, cy = 0.0f;
#pragma unroll
    for (int i = 0; i < RPC; i++) {
        const float2 f = __half22float2(sp2[i * 512 + tid]);
        cx = fmaf(f.x, iv[i], cx);
        cy = fmaf(f.y, iv[i], cy);
    }
    ((float2*)s_c)[tid] = make_float2(cx, cy);
    __syncthreads();

    if (tid == 0) bulk_reduce_add_4k(&d_colacc[k + 1][b << 10], s_c);
}

// ---------------------------------------------------------------------------
// Final: out_ij = P_ij * r_i * c_j with c_j = 1/colacc[ITERS][j].
// P read from (hot) L2 in fp16 — no exp2, no g re-read. Warp per row.
__global__ __launch_bounds__(256) void final_kernel(float* __restrict__ out) {
    __shared__ float s_ci[NN];
    const int row0 = blockIdx.x * 8;
    const int b    = row0 >> 10;

    for (int t = threadIdx.x; t < NN; t += 256)
        s_ci[t] = __fdividef(1.0f, d_colacc[ITERS][(b << 10) + t]);
    __syncthreads();

    const int warp = threadIdx.x >> 5, lane = threadIdx.x & 31;
    const int row  = row0 + warp;
    const float rv = d_r[row];

    const uint2*  pr  = (const uint2*)(d_P + (size_t)row * NN);
    const float4* ci4 = (const float4*)s_ci;
    float4*       orw = (float4*)(out + (size_t)row * NN);

#pragma unroll
    for (int k = 0; k < 8; k++) {
        const int idx = lane + 32 * k;
        const uint2 pv = __ldcg(&pr[idx]);
        const float2 f0 = __half22float2(*(const __half2*)&pv.x);
        const float2 f1 = __half22float2(*(const __half2*)&pv.y);
        const float4 cv = ci4[idx];
        float4 o;
        o.x = f0.x * rv * cv.x;
        o.y = f0.y * rv * cv.y;
        o.z = f1.x * rv * cv.z;
        o.w = f1.y * rv * cv.w;
        orw[idx] = o;
    }
}

// ---------------------------------------------------------------------------
extern "C" void kernel_launch(void* const* d_in, const int* in_sizes, int n_in,
                              void* d_out, int out_size) {
    // Only the gumbel tensor matters (score projection cancels in the first
    // row normalization).
    const float* g = nullptr;
    for (int i = 0; i < n_in; i++)
        if (in_sizes[i] == NB * NN * NN) g = (const float*)d_in[i];
    float* out = (float*)d_out;

    const int PRE_SMEM  = RPC * NN * 2 + NN * 4 + RPC * 4;                 // 36928
    const int FAST_SMEM = 2 * RPC * NN * 2 + NN * 2 + NN * 4 + 2 * RPC * 4 + 16;
    const int LAST_SMEM = RPC * NN * 2 + NN * 4 + RPC * 4;                 // 36928
    cudaFuncSetAttribute(pre_iter0_kernel,
                         cudaFuncAttributeMaxDynamicSharedMemorySize, PRE_SMEM);
    cudaFuncSetAttribute(iter_fast_kernel,
                         cudaFuncAttributeMaxDynamicSharedMemorySize, FAST_SMEM);
    cudaFuncSetAttribute(iter_last_kernel,
                         cudaFuncAttributeMaxDynamicSharedMemorySize, LAST_SMEM);

    init_kernel<<<ITERS * NB * NN / 512, 512>>>();             // zero buf[1..20]
    pre_iter0_kernel<<<NB * (NN / RPC), 512, PRE_SMEM>>>(g);   // P + iter 0

    for (int it = 1; it < ITERS - 1; it++)
        iter_fast_kernel<<<NB * (NN / (2 * RPC)), 512, FAST_SMEM>>>(it);
    iter_last_kernel<<<NB * (NN / RPC), 512, LAST_SMEM>>>();

    final_kernel<<<NB * NN / 8, 256>>>(out);
}

// round 17
// speedup vs baseline: 1.5709x; 1.0502x over previous
#include <cuda_runtime.h>
#include <cuda_fp16.h>
#include <math.h>

#define NB 32
#define NN 1024
#define L2E 1.4426950408889634f
#define RPC 16                   // rows per tile (pre/last kernels)
#define RPT 8                    // rows per tile (fast iteration kernel)
#define ITERS 20

// Static scratch (no allocation allowed). d_P = 64 MB fp16, L2-resident.
__device__ __half d_P[(size_t)NB * NN * NN];
__device__ float  d_r[NB * NN];               // last-iteration row scalings
// Rotating column accumulators: iter k reads buf[k] (c=1/buf[k]), TMA-reduces
// into buf[k+1]. buf[1..ITERS] zeroed once per launch.
__device__ float  d_colacc[ITERS + 1][NB * NN];

// ---------------------------------------------------------------------------
__device__ __forceinline__ unsigned smem_u32(const void* p) {
    return (unsigned)__cvta_generic_to_shared(p);
}

// One 4 KB smem->global add-reduction via the TMA engine.
__device__ __forceinline__ void bulk_reduce_add_4k(float* gdst, const float* ssrc) {
    asm volatile("fence.proxy.async.shared::cta;" ::: "memory");
    asm volatile(
        "cp.reduce.async.bulk.global.shared::cta.bulk_group.add.f32 [%0], [%1], %2;"
        :: "l"(gdst), "r"(smem_u32(ssrc)), "r"(NN * 4) : "memory");
    asm volatile("cp.async.bulk.commit_group;" ::: "memory");
    asm volatile("cp.async.bulk.wait_group 0;" ::: "memory");
}

// Blocking mbarrier wait, parity phase.
__device__ __forceinline__ void mbar_wait(unsigned mbar, unsigned parity) {
    unsigned done;
    asm volatile(
        "{\n\t.reg .pred p;\n\t"
        "mbarrier.try_wait.parity.acquire.cta.shared::cta.b64 p, [%1], %2;\n\t"
        "selp.b32 %0, 1, 0, p;\n\t}"
        : "=r"(done) : "r"(mbar), "r"(parity) : "memory");
    while (!done) {
        asm volatile(
            "{\n\t.reg .pred p;\n\t"
            "mbarrier.try_wait.parity.acquire.cta.shared::cta.b64 p, [%1], %2, 0x989680;\n\t"
            "selp.b32 %0, 1, 0, p;\n\t}"
            : "=r"(done) : "r"(mbar), "r"(parity) : "memory");
    }
}

__device__ __forceinline__ void tma_load_bytes(unsigned sdst, const __half* src,
                                               unsigned nbytes, unsigned mbar) {
    asm volatile(
        "mbarrier.arrive.expect_tx.shared.b64 _, [%0], %1;"
        :: "r"(mbar), "r"(nbytes) : "memory");
    asm volatile(
        "cp.async.bulk.shared::cta.global.mbarrier::complete_tx::bytes "
        "[%0], [%1], %2, [%3];"
        :: "r"(sdst), "l"(src), "r"(nbytes), "r"(mbar) : "memory");
}

// ---------------------------------------------------------------------------
// Zero buf[1..ITERS].
__global__ __launch_bounds__(512) void init_kernel() {
    ((float*)&d_colacc[1][0])[blockIdx.x * 512 + threadIdx.x] = 0.0f;
}

// ---------------------------------------------------------------------------
// Fused precompute + iteration 0. 64 CTAs/batch, 16 rows each (warp/row).
//   P_ij = exp2(g*L2E - M_i)  -> gmem (fp16) and smem tile
//   r^1_i = 1/sum_j P_ij
//   colacc[1]_j += sum_i P_ij r^1_i   (fp16 HFMA2 partials, TMA bulk reduce)
__global__ __launch_bounds__(512)
void pre_iter0_kernel(const float* __restrict__ g) {
    extern __shared__ float smem[];
    __half*  s_P  = (__half*)smem;                 // RPC*NN halfs = 32 KB
    float*   s_c  = smem + RPC * NN / 2;           // NN floats (col partials)
    __half2* s_rh = (__half2*)(s_c + NN);          // RPC half2 (r broadcast)

    const int tid  = threadIdx.x;
    const int b    = blockIdx.x >> 6;
    const int cib  = blockIdx.x & 63;
    const int warp = tid >> 5, lane = tid & 31;
    const int row  = (b << 10) + cib * RPC + warp;

    const float4* gr = (const float4*)(g + (size_t)row * NN);
    float4 v[8];
    float m = -1e30f;
#pragma unroll
    for (int k = 0; k < 8; k++) {
        v[k] = gr[lane + 32 * k];
        m = fmaxf(m, fmaxf(fmaxf(v[k].x, v[k].y), fmaxf(v[k].z, v[k].w)));
    }
#pragma unroll
    for (int o = 16; o; o >>= 1)
        m = fmaxf(m, __shfl_xor_sync(0xffffffffu, m, o));
    const float mb = m * L2E;

    uint2* pg = (uint2*)(d_P + (size_t)row * NN);
    uint2* sp = (uint2*)(s_P + warp * NN);
    float  s  = 0.0f;
#pragma unroll
    for (int k = 0; k < 8; k++) {
        const int idx = lane + 32 * k;
        const float ex = exp2f(fmaf(v[k].x, L2E, -mb));
        const float ey = exp2f(fmaf(v[k].y, L2E, -mb));
        const float ez = exp2f(fmaf(v[k].z, L2E, -mb));
        const float ew = exp2f(fmaf(v[k].w, L2E, -mb));
        __half2 h0 = __floats2half2_rn(ex, ey);
        __half2 h1 = __floats2half2_rn(ez, ew);
        uint2 u;
        u.x = *(const unsigned*)&h0;
        u.y = *(const unsigned*)&h1;
        pg[idx] = u;
        sp[idx] = u;
        s += (ex + ey) + (ez + ew);
    }
#pragma unroll
    for (int o = 16; o; o >>= 1)
        s += __shfl_xor_sync(0xffffffffu, s, o);
    const float r = __fdividef(1.0f, s);
    if (lane == 0) s_rh[warp] = __half2half2(__float2half_rn(r));
    __syncthreads();

    __half2 iv[RPC];
#pragma unroll
    for (int i = 0; i < RPC; i++) iv[i] = s_rh[i];

    const __half2* sp2 = (const __half2*)s_P;
    __half2 acc = __float2half2_rn(0.0f);
#pragma unroll
    for (int i = 0; i < RPC; i++)
        acc = __hfma2(sp2[i * 512 + tid], iv[i], acc);
    ((float2*)s_c)[tid] = __half22float2(acc);
    __syncthreads();

    if (tid == 0) bulk_reduce_add_4k(&d_colacc[1][b << 10], s_c);
}

// ---------------------------------------------------------------------------
// Phase A helper (fast kernel): warp-per-row sum of P*c over one 1024-wide
// row, with the c chunk pre-loaded into registers (reused across tiles).
__device__ __forceinline__ float rowsum_h2_reg(const __half* tile_row,
                                               const uint4* cv, int lane) {
    const uint4* p4 = (const uint4*)tile_row;
    float s = 0.0f;
#pragma unroll
    for (int kk = 0; kk < 4; kk++) {
        const uint4 pv = p4[lane + 32 * kk];
        const uint4 c  = cv[kk];
        __half2 hacc = __float2half2_rn(0.0f);
        hacc = __hfma2(*(const __half2*)&pv.x, *(const __half2*)&c.x, hacc);
        hacc = __hfma2(*(const __half2*)&pv.y, *(const __half2*)&c.y, hacc);
        hacc = __hfma2(*(const __half2*)&pv.z, *(const __half2*)&c.z, hacc);
        hacc = __hfma2(*(const __half2*)&pv.w, *(const __half2*)&c.w, hacc);
        const float2 f = __half22float2(hacc);
        s += f.x + f.y;
    }
#pragma unroll
    for (int o = 16; o; o >>= 1)
        s += __shfl_xor_sync(0xffffffffu, s, o);
    return s;
}

// Phase B helper (fast kernel): 8-term fp16 partials for this thread's 4
// columns, folded into fp32 accumulators.
__device__ __forceinline__ void colpart4_h2(const __half* tile, const __half2* rh,
                                            int tid, float4& acc) {
    __half2 iv[RPT];
#pragma unroll
    for (int i = 0; i < RPT; i++) iv[i] = rh[i];
    const uint2* sp2 = (const uint2*)tile;   // 2 half2 = 4 cols per slot
    __half2 a0 = __float2half2_rn(0.0f);
    __half2 a1 = __float2half2_rn(0.0f);
#pragma unroll
    for (int i = 0; i < RPT; i++) {
        const uint2 pv = sp2[i * 256 + tid];
        a0 = __hfma2(*(const __half2*)&pv.x, iv[i], a0);
        a1 = __hfma2(*(const __half2*)&pv.y, iv[i], a1);
    }
    const float2 f0 = __half22float2(a0);
    const float2 f1 = __half22float2(a1);
    acc.x += f0.x; acc.y += f0.y; acc.z += f1.x; acc.w += f1.y;
}

// ---------------------------------------------------------------------------
// Fast Sinkhorn iteration (k = 1..18). 64 CTAs/batch, TWO 8-row tiles each,
// 256 threads. Small jobs pack tightly: 6 CTAs/SM (smem ~34.9 KB, partials
// buffer aliased onto the dead tile0), 888 slots for 2048 jobs.
// Both TMA copies issued up-front; c chunk register-cached across tiles;
// column partials accumulate in fp32 registers -> ONE bulk reduce per CTA.
__global__ __launch_bounds__(256, 6)
void iter_fast_kernel(int k) {
    extern __shared__ __align__(128) char smem_raw[];
    __half*  s_P0  = (__half*)smem_raw;                          // 16 KB
    __half*  s_P1  = (__half*)(smem_raw + RPT * NN * 2);         // 16 KB
    __half2* s_ch  = (__half2*)(smem_raw + 2 * RPT * NN * 2);    // 2 KB
    __half2* s_rh0 = (__half2*)((char*)s_ch + NN * 2);           // 32 B
    __half2* s_rh1 = s_rh0 + RPT;                                // 32 B
    unsigned long long* s_mbar = (unsigned long long*)(s_rh1 + RPT);
    float*   s_part = (float*)s_P0;              // alias: tile0 dead by then

    const int tid  = threadIdx.x;
    const int b    = blockIdx.x >> 6;            // 64 CTAs per batch
    const int cib  = blockIdx.x & 63;
    const int warp = tid >> 5, lane = tid & 31;
    const unsigned mbar0 = smem_u32(s_mbar);
    const unsigned mbar1 = smem_u32(s_mbar + 1);

    if (tid == 0) {
        asm volatile("mbarrier.init.shared.b64 [%0], 1;" :: "r"(mbar0) : "memory");
        asm volatile("mbarrier.init.shared.b64 [%0], 1;" :: "r"(mbar1) : "memory");
    }
    __syncthreads();

    if (tid == 0) {
        const __half* src = d_P + ((size_t)((b << 10) + cib * 2 * RPT)) * NN;
        tma_load_bytes(smem_u32(s_P0), src, RPT * NN * 2, mbar0);
        tma_load_bytes(smem_u32(s_P1), src + (size_t)RPT * NN, RPT * NN * 2, mbar1);
    }

    // stage c = 1/colacc (overlaps both bulk copies); 4 values per thread
    {
        const float4 v = ((const float4*)&d_colacc[k][b << 10])[tid];
        s_ch[2 * tid]     = __floats2half2_rn(__fdividef(1.0f, v.x),
                                              __fdividef(1.0f, v.y));
        s_ch[2 * tid + 1] = __floats2half2_rn(__fdividef(1.0f, v.z),
                                              __fdividef(1.0f, v.w));
    }
    __syncthreads();            // c ready

    // cache this lane's c chunk in registers (shared by both tiles' phase A)
    uint4 cv[4];
#pragma unroll
    for (int kk = 0; kk < 4; kk++)
        cv[kk] = ((const uint4*)s_ch)[lane + 32 * kk];

    mbar_wait(mbar0, 0);        // tile0 ready (tile1 still streaming)

    // ---- tile0 phase A (warp per row, 8 rows) ----
    float s0 = rowsum_h2_reg(s_P0 + warp * NN, cv, lane);
    if (lane == 0)
        s_rh0[warp] = __half2half2(__float2half_rn(__fdividef(1.0f, s0)));
    __syncthreads();

    // ---- tile0 phase B (into registers) ----
    float4 acc = make_float4(0.0f, 0.0f, 0.0f, 0.0f);
    colpart4_h2(s_P0, s_rh0, tid, acc);

    // ---- tile1 phase A ----
    mbar_wait(mbar1, 0);
    float s1 = rowsum_h2_reg(s_P1 + warp * NN, cv, lane);
    if (lane == 0)
        s_rh1[warp] = __half2half2(__float2half_rn(__fdividef(1.0f, s1)));
    __syncthreads();            // also fences all tile0 reads (s_part alias)

    // ---- tile1 phase B ----
    colpart4_h2(s_P1, s_rh1, tid, acc);

    ((float4*)s_part)[tid] = acc;    // aliases s_P0 (dead)
    __syncthreads();

    if (tid == 0) bulk_reduce_add_4k(&d_colacc[k + 1][b << 10], s_part);
}

// ---------------------------------------------------------------------------
// Last iteration (k = 19), fully fp32: its r and colacc feed the output.
__global__ __launch_bounds__(512, 3)
void iter_last_kernel() {
    extern __shared__ float smem[];
    __half* s_P = (__half*)smem;                   // RPC*NN halfs
    float*  s_c = smem + RPC * NN / 2;             // NN floats (c, then partials)
    float*  s_r = s_c + NN;                        // RPC floats

    const int k    = ITERS - 1;
    const int tid  = threadIdx.x;
    const int b    = blockIdx.x >> 6;
    const int cib  = blockIdx.x & 63;
    const int warp = tid >> 5, lane = tid & 31;

    {
        const float* br = &d_colacc[k][b << 10];
        s_c[tid]       = __fdividef(1.0f, br[tid]);
        s_c[tid + 512] = __fdividef(1.0f, br[tid + 512]);
    }
    __syncthreads();

    const int row = (b << 10) + cib * RPC + warp;
    const uint2*  pr  = (const uint2*)(d_P + (size_t)row * NN);
    uint2*        spr = (uint2*)(s_P + warp * NN);
    const float4* c4  = (const float4*)s_c;

    float s = 0.0f;
#pragma unroll
    for (int kk = 0; kk < 8; kk++) {
        const int idx = lane + 32 * kk;
        const uint2 pv = __ldcg(&pr[idx]);
        spr[idx] = pv;
        const float2 f0 = __half22float2(*(const __half2*)&pv.x);
        const float2 f1 = __half22float2(*(const __half2*)&pv.y);
        const float4 cv = c4[idx];
        s = fmaf(f0.x, cv.x, s);
        s = fmaf(f0.y, cv.y, s);
        s = fmaf(f1.x, cv.z, s);
        s = fmaf(f1.y, cv.w, s);
    }
#pragma unroll
    for (int o = 16; o; o >>= 1)
        s += __shfl_xor_sync(0xffffffffu, s, o);
    const float r = __fdividef(1.0f, s);
    if (lane == 0) {
        s_r[warp] = r;
        d_r[row]  = r;                             // feeds final_kernel
    }
    __syncthreads();

    float iv[RPC];
#pragma unroll
    for (int i = 0; i < RPC; i++) iv[i] = s_r[i];

    const __half2* sp2 = (const __half2*)s_P;
    float cx = 0.0f, cy = 0.0f;
#pragma unroll
    for (int i = 0; i < RPC; i++) {
        const float2 f = __half22float2(sp2[i * 512 + tid]);
        cx = fmaf(f.x, iv[i], cx);
        cy = fmaf(f.y, iv[i], cy);
    }
    ((float2*)s_c)[tid] = make_float2(cx, cy);
    __syncthreads();

    if (tid == 0) bulk_reduce_add_4k(&d_colacc[k + 1][b << 10], s_c);
}

// ---------------------------------------------------------------------------
// Final: out_ij = P_ij * r_i * c_j with c_j = 1/colacc[ITERS][j].
// P read from (hot) L2 in fp16 — no exp2, no g re-read. Warp per row.
__global__ __launch_bounds__(256) void final_kernel(float* __restrict__ out) {
    __shared__ float s_ci[NN];
    const int row0 = blockIdx.x * 8;
    const int b    = row0 >> 10;

    for (int t = threadIdx.x; t < NN; t += 256)
        s_ci[t] = __fdividef(1.0f, d_colacc[ITERS][(b << 10) + t]);
    __syncthreads();

    const int warp = threadIdx.x >> 5, lane = threadIdx.x & 31;
    const int row  = row0 + warp;
    const float rv = d_r[row];

    const uint2*  pr  = (const uint2*)(d_P + (size_t)row * NN);
    const float4* ci4 = (const float4*)s_ci;
    float4*       orw = (float4*)(out + (size_t)row * NN);

#pragma unroll
    for (int k = 0; k < 8; k++) {
        const int idx = lane + 32 * k;
        const uint2 pv = __ldcg(&pr[idx]);
        const float2 f0 = __half22float2(*(const __half2*)&pv.x);
        const float2 f1 = __half22float2(*(const __half2*)&pv.y);
        const float4 cv = ci4[idx];
        float4 o;
        o.x = f0.x * rv * cv.x;
        o.y = f0.y * rv * cv.y;
        o.z = f1.x * rv * cv.z;
        o.w = f1.y * rv * cv.w;
        orw[idx] = o;
    }
}

// ---------------------------------------------------------------------------
extern "C" void kernel_launch(void* const* d_in, const int* in_sizes, int n_in,
                              void* d_out, int out_size) {
    // Only the gumbel tensor matters (score projection cancels in the first
    // row normalization).
    const float* g = nullptr;
    for (int i = 0; i < n_in; i++)
        if (in_sizes[i] == NB * NN * NN) g = (const float*)d_in[i];
    float* out = (float*)d_out;

    const int PRE_SMEM  = RPC * NN * 2 + NN * 4 + RPC * 4;                   // 36928
    const int FAST_SMEM = 2 * RPT * NN * 2 + NN * 2 + 2 * RPT * 4 + 16;      // 34896
    const int LAST_SMEM = RPC * NN * 2 + NN * 4 + RPC * 4;                   // 36928
    cudaFuncSetAttribute(pre_iter0_kernel,
                         cudaFuncAttributeMaxDynamicSharedMemorySize, PRE_SMEM);
    cudaFuncSetAttribute(iter_fast_kernel,
                         cudaFuncAttributeMaxDynamicSharedMemorySize, FAST_SMEM);
    cudaFuncSetAttribute(iter_last_kernel,
                         cudaFuncAttributeMaxDynamicSharedMemorySize, LAST_SMEM);

    init_kernel<<<ITERS * NB * NN / 512, 512>>>();             // zero buf[1..20]
    pre_iter0_kernel<<<NB * (NN / RPC), 512, PRE_SMEM>>>(g);   // P + iter 0

    for (int it = 1; it < ITERS - 1; it++)
        iter_fast_kernel<<<NB * (NN / (2 * RPT)), 256, FAST_SMEM>>>(it);
    iter_last_kernel<<<NB * (NN / RPC), 512, LAST_SMEM>>>();

    final_kernel<<<NB * NN / 8, 256>>>(out);
}